// round 12
// baseline (speedup 1.0000x reference)
#include <cuda_runtime.h>
#include <cuda_bf16.h>
#include <cstdint>

#define BATCH 2048
#define SEQ   64
#define DIN   512
#define HID   1024
#define CIN   1536
#define WSZ   (HID*CIN)

#define BM 128
#define BN 64          // per gate
#define BK 64
#define THREADS 256

// rows have 128B of data on a 144B pitch (odd 16B-granule multiplier -> conflict-free ldmatrix)
#define PITCH 144
#define A_TILE  (128*PITCH)          // 18432 B (one of hi/lo)
#define B_TILE  (64*PITCH)           // 9216 B  (one gate, one of hi/lo)
#define OFF_A   0                    // Ahi, Alo
#define OFF_B   (2*A_TILE)           // B[g][p]
#define STAGE   (2*A_TILE + 6*B_TILE)   // 92160 B
#define TILES_OFF 1024               // biases live below
#define SMEM_DYN (TILES_OFF + 2*STAGE)  // 185344 B

// ---------------- device globals ----------------
__device__ __nv_bfloat16 g_xhi[(size_t)BATCH * SEQ * DIN];
__device__ __nv_bfloat16 g_xlo[(size_t)BATCH * SEQ * DIN];
__device__ __nv_bfloat16 g_whi[3 * WSZ];
__device__ __nv_bfloat16 g_wlo[3 * WSZ];
__device__ __nv_bfloat16 g_hhi[2][BATCH * HID];
__device__ __nv_bfloat16 g_hlo[2][BATCH * HID];

// ---------------- asm helpers ----------------
__device__ __forceinline__ uint32_t smem_u32(const void* p) {
    uint32_t a;
    asm("{ .reg .u64 t; cvta.to.shared.u64 t, %1; cvt.u32.u64 %0, t; }" : "=r"(a) : "l"(p));
    return a;
}
__device__ __forceinline__ void cp16(uint32_t dst, const void* src) {
    asm volatile("cp.async.cg.shared.global [%0], [%1], 16;" :: "r"(dst), "l"(src));
}
__device__ __forceinline__ void cp_commit() {
    asm volatile("cp.async.commit_group;" ::: "memory");
}
template <int N>
__device__ __forceinline__ void cp_wait() {
    asm volatile("cp.async.wait_group %0;" :: "n"(N) : "memory");
}
__device__ __forceinline__ void ldmx4(uint32_t* r, uint32_t addr) {
    asm volatile("ldmatrix.sync.aligned.m8n8.x4.shared.b16 {%0,%1,%2,%3}, [%4];"
                 : "=r"(r[0]), "=r"(r[1]), "=r"(r[2]), "=r"(r[3]) : "r"(addr));
}
__device__ __forceinline__ void mma16816(float* c, const uint32_t* a,
                                         uint32_t b0, uint32_t b1) {
    asm volatile(
        "mma.sync.aligned.m16n8k16.row.col.f32.bf16.bf16.f32 "
        "{%0,%1,%2,%3}, {%4,%5,%6,%7}, {%8,%9}, {%0,%1,%2,%3};"
        : "+f"(c[0]), "+f"(c[1]), "+f"(c[2]), "+f"(c[3])
        : "r"(a[0]), "r"(a[1]), "r"(a[2]), "r"(a[3]), "r"(b0), "r"(b1));
}

// ---------------- split kernels (fp32 -> bf16 hi/lo) ----------------
__device__ __forceinline__ void split8(const float4 v0, const float4 v1,
                                       uint4* hi, uint4* lo) {
    float f[8] = {v0.x, v0.y, v0.z, v0.w, v1.x, v1.y, v1.z, v1.w};
    __nv_bfloat16 h[8], l[8];
#pragma unroll
    for (int i = 0; i < 8; i++) {
        h[i] = __float2bfloat16(f[i]);
        l[i] = __float2bfloat16(f[i] - __bfloat162float(h[i]));
    }
    *hi = *(const uint4*)h;
    *lo = *(const uint4*)l;
}

__global__ __launch_bounds__(256)
void split_x_kernel(const float* __restrict__ src) {
    size_t i8 = ((size_t)blockIdx.x * 256 + threadIdx.x) * 8;
    const float4* s = (const float4*)(src + i8);
    uint4 hi, lo;
    split8(s[0], s[1], &hi, &lo);
    *(uint4*)(g_xhi + i8) = hi;
    *(uint4*)(g_xlo + i8) = lo;
}

__global__ __launch_bounds__(256)
void split_w_kernel(const float* __restrict__ wf, const float* __restrict__ wg,
                    const float* __restrict__ wh) {
    size_t i8 = ((size_t)blockIdx.x * 256 + threadIdx.x) * 8;
    int gate = (int)(i8 / WSZ);
    size_t off = i8 - (size_t)gate * WSZ;
    const float* src = (gate == 0) ? wf : (gate == 1) ? wg : wh;
    const float4* s = (const float4*)(src + off);
    uint4 hi, lo;
    split8(s[0], s[1], &hi, &lo);
    *(uint4*)(g_whi + i8) = hi;
    *(uint4*)(g_wlo + i8) = lo;
}

// ---------------- step kernel ----------------
extern __shared__ char s_raw[];

__global__ __launch_bounds__(THREADS, 1)
void lnn_step(const float* __restrict__ bf, const float* __restrict__ bg,
              const float* __restrict__ bh, int t, int dst, int nchunks)
{
    const int tid  = threadIdx.x;
    const int wid  = tid >> 5;
    const int lane = tid & 31;
    const int wm   = wid & 3;      // 0..3  (M)
    const int wn   = wid >> 2;     // 0..1  (N)
    const int m0   = blockIdx.x * BM;
    const int n0   = blockIdx.y * BN;

    const __nv_bfloat16* hhi = g_hhi[dst ^ 1];
    const __nv_bfloat16* hlo = g_hlo[dst ^ 1];

    float* sb = (float*)s_raw;                      // sb[3][64]
    if (tid < 192) {
        int g = tid >> 6, j = tid & 63;
        const float* b = (g == 0) ? bf : (g == 1) ? bg : bh;
        sb[tid] = b[n0 + j];
    }

    const uint32_t tiles = smem_u32(s_raw) + TILES_OFF;

    // ---- stage fill (cp.async), BK=64: 16B chunks, 8 per row ----
    auto fill = [&](int buf, int k0) {
        const uint32_t stg = tiles + buf * STAGE;
        const bool inx = (k0 < DIN);
#pragma unroll
        for (int it = 0; it < 8; it++) {            // A: 2048 x 16B
            int i = tid + it * THREADS;
            int p = i >> 10, r = (i >> 3) & 127, c = i & 7;
            uint32_t d = stg + OFF_A + p * A_TILE + r * PITCH + c * 16;
            const __nv_bfloat16* s;
            if (inx)
                s = (p ? g_xlo : g_xhi) + (size_t)(m0 + r) * (SEQ * DIN)
                    + (size_t)t * DIN + k0 + c * 8;
            else
                s = (p ? hlo : hhi) + (size_t)(m0 + r) * HID + (k0 - DIN) + c * 8;
            cp16(d, s);
        }
#pragma unroll
        for (int it = 0; it < 12; it++) {           // B: 3072 x 16B
            int i = tid + it * THREADS;
            int g = i >> 10, j = i & 1023;
            int p = j >> 9, r = (j >> 3) & 63, c = j & 7;
            uint32_t d = stg + OFF_B + (g * 2 + p) * B_TILE + r * PITCH + c * 16;
            const __nv_bfloat16* s = (p ? g_wlo : g_whi) + (size_t)g * WSZ
                                     + (size_t)(n0 + r) * CIN + k0 + c * 8;
            cp16(d, s);
        }
        cp_commit();
    };

    float acc[3][2][4][4];
#pragma unroll
    for (int g = 0; g < 3; g++)
#pragma unroll
        for (int mt = 0; mt < 2; mt++)
#pragma unroll
            for (int nt = 0; nt < 4; nt++)
#pragma unroll
                for (int r = 0; r < 4; r++) acc[g][mt][nt][r] = 0.f;

    // per-thread ldmatrix base offsets
    const uint32_t aoff = (uint32_t)((wm * 32 + (lane & 15)) * PITCH + (lane >> 4) * 16);
    const uint32_t boff = (uint32_t)((wn * 32 + (lane & 7) + ((lane >> 4) << 3)) * PITCH
                                     + ((lane >> 3) & 1) * 16);

    // fragment buffers: A and gate-0 B double-buffered across k16; B1/B2 single
    uint32_t ahi[2][2][4], alo[2][2][4];     // [buf][mt][4]
    uint32_t b0h[2][2][4], b0l[2][2][4];     // [buf][nt2][4]
    uint32_t b1h[2][4], b1l[2][4], b2h[2][4], b2l[2][4];

    // 8 MMAs: one split-product over the full warp tile for gate g
    auto prodA = [&](int g, uint32_t a[2][4], uint32_t b[2][4]) {
#pragma unroll
        for (int mt = 0; mt < 2; mt++)
#pragma unroll
            for (int nt = 0; nt < 4; nt++) {
                const int n2 = nt >> 1, br = (nt & 1) * 2;
                mma16816(acc[g][mt][nt], a[mt], b[n2][br], b[n2][br + 1]);
            }
    };

    fill(0, 0);
    for (int ch = 0; ch < nchunks; ch++) {
        cp_wait<0>();
        __syncthreads();                 // single barrier per chunk
        if (ch + 1 < nchunks) fill((ch + 1) & 1, (ch + 1) * BK);

        const uint32_t stg = tiles + (ch & 1) * STAGE;

        // prologue for k16 = 0
#pragma unroll
        for (int mt = 0; mt < 2; mt++) {
            ldmx4(ahi[0][mt], stg + OFF_A + 0      + mt * (16 * PITCH) + aoff);
            ldmx4(alo[0][mt], stg + OFF_A + A_TILE + mt * (16 * PITCH) + aoff);
        }
        {
            uint32_t bb = stg + OFF_B + boff;
            ldmx4(b0h[0][0], bb);
            ldmx4(b0h[0][1], bb + 16 * PITCH);
            ldmx4(b0l[0][0], bb + B_TILE);
            ldmx4(b0l[0][1], bb + B_TILE + 16 * PITCH);
        }

#pragma unroll
        for (int k16 = 0; k16 < 4; k16++) {
            const int cur = k16 & 1, nxt = cur ^ 1;
            const uint32_t kb  = k16 * 32;
            const uint32_t kbn = kb + 32;

            // gate 0 (B0 from regs), interleave B1 loads
            prodA(0, ahi[cur], b0h[cur]);
            {
                uint32_t bb = stg + OFF_B + 2 * B_TILE + kb + boff;
                ldmx4(b1h[0], bb);
                ldmx4(b1h[1], bb + 16 * PITCH);
            }
            prodA(0, ahi[cur], b0l[cur]);
            {
                uint32_t bb = stg + OFF_B + 3 * B_TILE + kb + boff;
                ldmx4(b1l[0], bb);
                ldmx4(b1l[1], bb + 16 * PITCH);
            }
            prodA(0, alo[cur], b0h[cur]);

            // gate 1, interleave B2 loads
            prodA(1, ahi[cur], b1h);
            {
                uint32_t bb = stg + OFF_B + 4 * B_TILE + kb + boff;
                ldmx4(b2h[0], bb);
                ldmx4(b2h[1], bb + 16 * PITCH);
            }
            prodA(1, ahi[cur], b1l);
            {
                uint32_t bb = stg + OFF_B + 5 * B_TILE + kb + boff;
                ldmx4(b2l[0], bb);
                ldmx4(b2l[1], bb + 16 * PITCH);
            }
            prodA(1, alo[cur], b1h);

            // gate 2, interleave next-k16 A/B0 prefetch
            prodA(2, ahi[cur], b2h);
            if (k16 < 3) {
#pragma unroll
                for (int mt = 0; mt < 2; mt++) {
                    ldmx4(ahi[nxt][mt], stg + OFF_A + 0      + mt * (16 * PITCH) + kbn + aoff);
                    ldmx4(alo[nxt][mt], stg + OFF_A + A_TILE + mt * (16 * PITCH) + kbn + aoff);
                }
            }
            prodA(2, ahi[cur], b2l);
            if (k16 < 3) {
                uint32_t bb = stg + OFF_B + kbn + boff;
                ldmx4(b0h[nxt][0], bb);
                ldmx4(b0h[nxt][1], bb + 16 * PITCH);
                ldmx4(b0l[nxt][0], bb + B_TILE);
                ldmx4(b0l[nxt][1], bb + B_TILE + 16 * PITCH);
            }
            prodA(2, alo[cur], b2h);
        }
    }

    // ---- epilogue: bias + sigmoid gate, write h hi/lo ----
    __nv_bfloat16* ohi = g_hhi[dst];
    __nv_bfloat16* olo = g_hlo[dst];
#pragma unroll
    for (int mt = 0; mt < 2; mt++)
#pragma unroll
        for (int nt = 0; nt < 4; nt++)
#pragma unroll
            for (int rh = 0; rh < 2; rh++) {
                const int row  = m0 + wm * 32 + mt * 16 + (lane >> 2) + rh * 8;
                const int colb = wn * 32 + nt * 8 + (lane & 3) * 2;   // block-local
                float v[2], vl[2];
#pragma unroll
                for (int q = 0; q < 2; q++) {
                    const float fo = acc[0][mt][nt][2 * rh + q] + sb[colb + q];
                    const float go = acc[1][mt][nt][2 * rh + q] + sb[64 + colb + q];
                    const float ho = acc[2][mt][nt][2 * rh + q] + sb[128 + colb + q];
                    const float gate = 1.0f / (1.0f + __expf(fo));    // sigmoid(-f)
                    const float val = gate * go + (1.0f - gate) * ho;
                    const __nv_bfloat16 hi = __float2bfloat16(val);
                    v[q]  = __bfloat162float(hi);
                    vl[q] = val - v[q];
                }
                const size_t o = (size_t)row * HID + n0 + colb;
                __nv_bfloat162 phi, plo;
                phi.x = __float2bfloat16(v[0]);  phi.y = __float2bfloat16(v[1]);
                plo.x = __float2bfloat16(vl[0]); plo.y = __float2bfloat16(vl[1]);
                *(__nv_bfloat162*)(ohi + o) = phi;
                *(__nv_bfloat162*)(olo + o) = plo;
            }
}

// ---------------- FC head ----------------
__global__ __launch_bounds__(256)
void lnn_fc(const float* __restrict__ Wfc, const float* __restrict__ bfc,
            float* __restrict__ out, int src)
{
    const int b = blockIdx.x * blockDim.x + threadIdx.x;
    if (b >= BATCH) return;
    const __nv_bfloat16* hh = g_hhi[src] + (size_t)b * HID;
    const __nv_bfloat16* hl = g_hlo[src] + (size_t)b * HID;
    const float* w0 = Wfc;
    const float* w1 = Wfc + HID;
    float s0 = 0.f, s1 = 0.f;
#pragma unroll 8
    for (int i = 0; i < HID; i++) {
        float h = __bfloat162float(hh[i]) + __bfloat162float(hl[i]);
        s0 += h * w0[i];
        s1 += h * w1[i];
    }
    out[b * 2 + 0] = s0 + bfc[0];
    out[b * 2 + 1] = s1 + bfc[1];
}

// ---------------- launch ----------------
extern "C" void kernel_launch(void* const* d_in, const int* in_sizes, int n_in,
                              void* d_out, int out_size)
{
    const float* x   = (const float*)d_in[0];
    const float* Wf  = (const float*)d_in[1];
    const float* bf  = (const float*)d_in[2];
    const float* Wg  = (const float*)d_in[3];
    const float* bg  = (const float*)d_in[4];
    const float* Wh  = (const float*)d_in[5];
    const float* bh  = (const float*)d_in[6];
    const float* Wfc = (const float*)d_in[7];
    const float* bfc = (const float*)d_in[8];
    float* out = (float*)d_out;

    cudaFuncSetAttribute(lnn_step, cudaFuncAttributeMaxDynamicSharedMemorySize, SMEM_DYN);

    split_x_kernel<<<(BATCH * SEQ * DIN) / 2048, 256>>>(x);
    split_w_kernel<<<(3 * WSZ) / 2048, 256>>>(Wf, Wg, Wh);

    dim3 grid(BATCH / BM, HID / BN);   // 16 x 16 = 256 CTAs
    for (int t = 0; t < SEQ; t++) {
        lnn_step<<<grid, THREADS, SMEM_DYN>>>(bf, bg, bh, t, t & 1,
                                              (t == 0) ? (DIN / BK) : (CIN / BK));
    }
    lnn_fc<<<BATCH / 256, 256>>>(Wfc, bfc, out, 1);
}

// round 13
// speedup vs baseline: 1.4361x; 1.4361x over previous
#include <cuda_runtime.h>
#include <cuda_fp16.h>
#include <cstdint>

#define BATCH 2048
#define SEQ   64
#define DIN   512
#define HID   1024
#define CIN   1536
#define WSZ   (HID*CIN)

#define BM 128
#define BN 64          // per gate
#define BK 64
#define THREADS 256

// rows have 128B of data on a 144B pitch (odd 16B-granule multiplier -> conflict-free ldmatrix)
#define PITCH 144
#define A_TILE  (128*PITCH)          // 18432 B (one of hi/lo)
#define B_TILE  (64*PITCH)           // 9216 B  (one gate, single fp16)
#define OFF_A   0                    // Ahi, Alo
#define OFF_B   (2*A_TILE)           // B[g], g=0..2
#define STAGE   (2*A_TILE + 3*B_TILE)   // 64512 B
#define TILES_OFF 1024               // biases live below
#define SMEM_DYN (TILES_OFF + 2*STAGE)  // 130048 B

// ---------------- device globals ----------------
__device__ __half g_xhi[(size_t)BATCH * SEQ * DIN];
__device__ __half g_xlo[(size_t)BATCH * SEQ * DIN];
__device__ __half g_w[3 * WSZ];                    // weights: single fp16
__device__ __half g_hhi[2][BATCH * HID];
__device__ __half g_hlo[2][BATCH * HID];

// ---------------- asm helpers ----------------
__device__ __forceinline__ uint32_t smem_u32(const void* p) {
    uint32_t a;
    asm("{ .reg .u64 t; cvta.to.shared.u64 t, %1; cvt.u32.u64 %0, t; }" : "=r"(a) : "l"(p));
    return a;
}
__device__ __forceinline__ void cp16(uint32_t dst, const void* src) {
    asm volatile("cp.async.cg.shared.global [%0], [%1], 16;" :: "r"(dst), "l"(src));
}
__device__ __forceinline__ void cp_commit() {
    asm volatile("cp.async.commit_group;" ::: "memory");
}
template <int N>
__device__ __forceinline__ void cp_wait() {
    asm volatile("cp.async.wait_group %0;" :: "n"(N) : "memory");
}
__device__ __forceinline__ void ldmx4(uint32_t* r, uint32_t addr) {
    asm volatile("ldmatrix.sync.aligned.m8n8.x4.shared.b16 {%0,%1,%2,%3}, [%4];"
                 : "=r"(r[0]), "=r"(r[1]), "=r"(r[2]), "=r"(r[3]) : "r"(addr));
}
__device__ __forceinline__ void mma16816(float* c, const uint32_t* a,
                                         uint32_t b0, uint32_t b1) {
    asm volatile(
        "mma.sync.aligned.m16n8k16.row.col.f32.f16.f16.f32 "
        "{%0,%1,%2,%3}, {%4,%5,%6,%7}, {%8,%9}, {%0,%1,%2,%3};"
        : "+f"(c[0]), "+f"(c[1]), "+f"(c[2]), "+f"(c[3])
        : "r"(a[0]), "r"(a[1]), "r"(a[2]), "r"(a[3]), "r"(b0), "r"(b1));
}

// ---------------- split kernels ----------------
__global__ __launch_bounds__(256)
void split_x_kernel(const float* __restrict__ src) {
    size_t i8 = ((size_t)blockIdx.x * 256 + threadIdx.x) * 8;
    const float4* s = (const float4*)(src + i8);
    float f[8];
    *(float4*)(f + 0) = s[0];
    *(float4*)(f + 4) = s[1];
    __half h[8], l[8];
#pragma unroll
    for (int i = 0; i < 8; i++) {
        h[i] = __float2half(f[i]);
        l[i] = __float2half(f[i] - __half2float(h[i]));
    }
    *(uint4*)(g_xhi + i8) = *(const uint4*)h;
    *(uint4*)(g_xlo + i8) = *(const uint4*)l;
}

__global__ __launch_bounds__(256)
void split_w_kernel(const float* __restrict__ wf, const float* __restrict__ wg,
                    const float* __restrict__ wh) {
    size_t i8 = ((size_t)blockIdx.x * 256 + threadIdx.x) * 8;
    int gate = (int)(i8 / WSZ);
    size_t off = i8 - (size_t)gate * WSZ;
    const float* src = (gate == 0) ? wf : (gate == 1) ? wg : wh;
    const float4* s = (const float4*)(src + off);
    float f[8];
    *(float4*)(f + 0) = s[0];
    *(float4*)(f + 4) = s[1];
    __half h[8];
#pragma unroll
    for (int i = 0; i < 8; i++) h[i] = __float2half(f[i]);
    *(uint4*)(g_w + i8) = *(const uint4*)h;
}

// ---------------- step kernel ----------------
extern __shared__ char s_raw[];

__global__ __launch_bounds__(THREADS, 1)
void lnn_step(const float* __restrict__ bf, const float* __restrict__ bg,
              const float* __restrict__ bh, int t, int dst, int nchunks)
{
    const int tid  = threadIdx.x;
    const int wid  = tid >> 5;
    const int lane = tid & 31;
    const int wm   = wid & 3;      // 0..3  (M)
    const int wn   = wid >> 2;     // 0..1  (N)
    const int m0   = blockIdx.x * BM;
    const int n0   = blockIdx.y * BN;

    const __half* hhi = g_hhi[dst ^ 1];
    const __half* hlo = g_hlo[dst ^ 1];

    float* sb = (float*)s_raw;                      // sb[3][64]
    if (tid < 192) {
        int g = tid >> 6, j = tid & 63;
        const float* b = (g == 0) ? bf : (g == 1) ? bg : bh;
        sb[tid] = b[n0 + j];
    }

    const uint32_t tiles = smem_u32(s_raw) + TILES_OFF;

    // ---- stage fill (cp.async), BK=64: 16B chunks, 8 per row ----
    auto fill = [&](int buf, int k0) {
        const uint32_t stg = tiles + buf * STAGE;
        const bool inx = (k0 < DIN);
#pragma unroll
        for (int it = 0; it < 8; it++) {            // A: 2048 x 16B (hi+lo)
            int i = tid + it * THREADS;
            int p = i >> 10, r = (i >> 3) & 127, c = i & 7;
            uint32_t d = stg + OFF_A + p * A_TILE + r * PITCH + c * 16;
            const __half* s;
            if (inx)
                s = (p ? g_xlo : g_xhi) + (size_t)(m0 + r) * (SEQ * DIN)
                    + (size_t)t * DIN + k0 + c * 8;
            else
                s = (p ? hlo : hhi) + (size_t)(m0 + r) * HID + (k0 - DIN) + c * 8;
            cp16(d, s);
        }
#pragma unroll
        for (int it = 0; it < 6; it++) {            // B: 1536 x 16B (3 gates, single)
            int i = tid + it * THREADS;
            int g = i >> 9, r = (i >> 3) & 63, c = i & 7;
            uint32_t d = stg + OFF_B + g * B_TILE + r * PITCH + c * 16;
            const __half* s = g_w + (size_t)g * WSZ + (size_t)(n0 + r) * CIN + k0 + c * 8;
            cp16(d, s);
        }
        cp_commit();
    };

    float acc[3][2][4][4];
#pragma unroll
    for (int g = 0; g < 3; g++)
#pragma unroll
        for (int mt = 0; mt < 2; mt++)
#pragma unroll
            for (int nt = 0; nt < 4; nt++)
#pragma unroll
                for (int r = 0; r < 4; r++) acc[g][mt][nt][r] = 0.f;

    // per-thread ldmatrix base offsets
    const uint32_t aoff = (uint32_t)((wm * 32 + (lane & 15)) * PITCH + (lane >> 4) * 16);
    const uint32_t boff = (uint32_t)((wn * 32 + (lane & 7) + ((lane >> 4) << 3)) * PITCH
                                     + ((lane >> 3) & 1) * 16);

    // fragment buffers: A and gate-0 B double-buffered across k16; B1/B2 single
    uint32_t ahi[2][2][4], alo[2][2][4];     // [buf][mt][4]
    uint32_t b0[2][2][4];                    // [buf][nt2][4]
    uint32_t b1[2][4], b2[2][4];

    // 8 MMAs: one pass over the full warp tile for gate g
    auto prodA = [&](int g, uint32_t a[2][4], uint32_t b[2][4]) {
#pragma unroll
        for (int mt = 0; mt < 2; mt++)
#pragma unroll
            for (int nt = 0; nt < 4; nt++) {
                const int n2 = nt >> 1, br = (nt & 1) * 2;
                mma16816(acc[g][mt][nt], a[mt], b[n2][br], b[n2][br + 1]);
            }
    };

    fill(0, 0);
    for (int ch = 0; ch < nchunks; ch++) {
        cp_wait<0>();
        __syncthreads();                 // single barrier per chunk
        if (ch + 1 < nchunks) fill((ch + 1) & 1, (ch + 1) * BK);

        const uint32_t stg = tiles + (ch & 1) * STAGE;

        // prologue for k16 = 0
#pragma unroll
        for (int mt = 0; mt < 2; mt++) {
            ldmx4(ahi[0][mt], stg + OFF_A + 0      + mt * (16 * PITCH) + aoff);
            ldmx4(alo[0][mt], stg + OFF_A + A_TILE + mt * (16 * PITCH) + aoff);
        }
        {
            uint32_t bb = stg + OFF_B + boff;
            ldmx4(b0[0][0], bb);
            ldmx4(b0[0][1], bb + 16 * PITCH);
        }

#pragma unroll
        for (int k16 = 0; k16 < 4; k16++) {
            const int cur = k16 & 1, nxt = cur ^ 1;
            const uint32_t kb  = k16 * 32;
            const uint32_t kbn = kb + 32;

            // gate 0 (B0 from regs), interleave B1/B2 loads
            prodA(0, ahi[cur], b0[cur]);
            {
                uint32_t bb = stg + OFF_B + 1 * B_TILE + kb + boff;
                ldmx4(b1[0], bb);
                ldmx4(b1[1], bb + 16 * PITCH);
            }
            prodA(0, alo[cur], b0[cur]);
            {
                uint32_t bb = stg + OFF_B + 2 * B_TILE + kb + boff;
                ldmx4(b2[0], bb);
                ldmx4(b2[1], bb + 16 * PITCH);
            }

            // gate 1, interleave next-k16 A prefetch
            prodA(1, ahi[cur], b1);
            if (k16 < 3) {
#pragma unroll
                for (int mt = 0; mt < 2; mt++) {
                    ldmx4(ahi[nxt][mt], stg + OFF_A + 0      + mt * (16 * PITCH) + kbn + aoff);
                    ldmx4(alo[nxt][mt], stg + OFF_A + A_TILE + mt * (16 * PITCH) + kbn + aoff);
                }
            }
            prodA(1, alo[cur], b1);

            // gate 2, interleave next-k16 B0 prefetch
            prodA(2, ahi[cur], b2);
            if (k16 < 3) {
                uint32_t bb = stg + OFF_B + kbn + boff;
                ldmx4(b0[nxt][0], bb);
                ldmx4(b0[nxt][1], bb + 16 * PITCH);
            }
            prodA(2, alo[cur], b2);
        }
    }

    // ---- epilogue: bias + sigmoid gate, write h hi/lo ----
    __half* ohi = g_hhi[dst];
    __half* olo = g_hlo[dst];
#pragma unroll
    for (int mt = 0; mt < 2; mt++)
#pragma unroll
        for (int nt = 0; nt < 4; nt++)
#pragma unroll
            for (int rh = 0; rh < 2; rh++) {
                const int row  = m0 + wm * 32 + mt * 16 + (lane >> 2) + rh * 8;
                const int colb = wn * 32 + nt * 8 + (lane & 3) * 2;   // block-local
                __half vhi[2], vlo[2];
#pragma unroll
                for (int q = 0; q < 2; q++) {
                    const float fo = acc[0][mt][nt][2 * rh + q] + sb[colb + q];
                    const float go = acc[1][mt][nt][2 * rh + q] + sb[64 + colb + q];
                    const float ho = acc[2][mt][nt][2 * rh + q] + sb[128 + colb + q];
                    const float gate = 1.0f / (1.0f + __expf(fo));    // sigmoid(-f)
                    const float val = gate * go + (1.0f - gate) * ho;
                    vhi[q] = __float2half(val);
                    vlo[q] = __float2half(val - __half2float(vhi[q]));
                }
                const size_t o = (size_t)row * HID + n0 + colb;
                *(uint32_t*)(ohi + o) = *(const uint32_t*)vhi;
                *(uint32_t*)(olo + o) = *(const uint32_t*)vlo;
            }
}

// ---------------- FC head ----------------
__global__ __launch_bounds__(256)
void lnn_fc(const float* __restrict__ Wfc, const float* __restrict__ bfc,
            float* __restrict__ out, int src)
{
    const int b = blockIdx.x * blockDim.x + threadIdx.x;
    if (b >= BATCH) return;
    const __half* hh = g_hhi[src] + (size_t)b * HID;
    const __half* hl = g_hlo[src] + (size_t)b * HID;
    const float* w0 = Wfc;
    const float* w1 = Wfc + HID;
    float s0 = 0.f, s1 = 0.f;
#pragma unroll 8
    for (int i = 0; i < HID; i++) {
        float h = __half2float(hh[i]) + __half2float(hl[i]);
        s0 += h * w0[i];
        s1 += h * w1[i];
    }
    out[b * 2 + 0] = s0 + bfc[0];
    out[b * 2 + 1] = s1 + bfc[1];
}

// ---------------- launch ----------------
extern "C" void kernel_launch(void* const* d_in, const int* in_sizes, int n_in,
                              void* d_out, int out_size)
{
    const float* x   = (const float*)d_in[0];
    const float* Wf  = (const float*)d_in[1];
    const float* bf  = (const float*)d_in[2];
    const float* Wg  = (const float*)d_in[3];
    const float* bg  = (const float*)d_in[4];
    const float* Wh  = (const float*)d_in[5];
    const float* bh  = (const float*)d_in[6];
    const float* Wfc = (const float*)d_in[7];
    const float* bfc = (const float*)d_in[8];
    float* out = (float*)d_out;

    cudaFuncSetAttribute(lnn_step, cudaFuncAttributeMaxDynamicSharedMemorySize, SMEM_DYN);

    split_x_kernel<<<(BATCH * SEQ * DIN) / 2048, 256>>>(x);
    split_w_kernel<<<(3 * WSZ) / 2048, 256>>>(Wf, Wg, Wh);

    dim3 grid(BATCH / BM, HID / BN);   // 16 x 16 = 256 CTAs
    for (int t = 0; t < SEQ; t++) {
        lnn_step<<<grid, THREADS, SMEM_DYN>>>(bf, bg, bh, t, t & 1,
                                              (t == 0) ? (DIN / BK) : (CIN / BK));
    }
    lnn_fc<<<BATCH / 256, 256>>>(Wfc, bfc, out, 1);
}

// round 15
// speedup vs baseline: 1.5031x; 1.0467x over previous
#include <cuda_runtime.h>
#include <cuda_fp16.h>
#include <cstdint>

#define BATCH 2048
#define SEQ   64
#define DIN   512
#define HID   1024
#define CIN   1536
#define WSZ   (HID*CIN)

#define BM 128
#define BN 64          // per gate
#define BK 64
#define THREADS 256

// rows have 128B of data on a 144B pitch (odd 16B-granule multiplier -> conflict-free ldmatrix)
#define PITCH 144
#define A_TILE  (128*PITCH)          // 18432 B (single fp16)
#define B_TILE  (64*PITCH)           // 9216 B  (one gate, single fp16)
#define OFF_A   0
#define OFF_B   A_TILE               // B[g], g=0..2
#define STAGE   (A_TILE + 3*B_TILE)  // 46080 B
#define TILES_OFF 1024               // biases live below
#define SMEM_DYN (TILES_OFF + 2*STAGE)  // 93184 B

// ---------------- device globals ----------------
__device__ __half g_x[(size_t)BATCH * SEQ * DIN];
__device__ __half g_w[3 * WSZ];
__device__ __half g_h[2][BATCH * HID];

// ---------------- asm helpers ----------------
__device__ __forceinline__ uint32_t smem_u32(const void* p) {
    uint32_t a;
    asm("{ .reg .u64 t; cvta.to.shared.u64 t, %1; cvt.u32.u64 %0, t; }" : "=r"(a) : "l"(p));
    return a;
}
__device__ __forceinline__ void cp16(uint32_t dst, const void* src) {
    asm volatile("cp.async.cg.shared.global [%0], [%1], 16;" :: "r"(dst), "l"(src));
}
__device__ __forceinline__ void cp_commit() {
    asm volatile("cp.async.commit_group;" ::: "memory");
}
template <int N>
__device__ __forceinline__ void cp_wait() {
    asm volatile("cp.async.wait_group %0;" :: "n"(N) : "memory");
}
__device__ __forceinline__ void ldmx4(uint32_t* r, uint32_t addr) {
    asm volatile("ldmatrix.sync.aligned.m8n8.x4.shared.b16 {%0,%1,%2,%3}, [%4];"
                 : "=r"(r[0]), "=r"(r[1]), "=r"(r[2]), "=r"(r[3]) : "r"(addr));
}
__device__ __forceinline__ void mma16816(float* c, const uint32_t* a,
                                         uint32_t b0, uint32_t b1) {
    asm volatile(
        "mma.sync.aligned.m16n8k16.row.col.f32.f16.f16.f32 "
        "{%0,%1,%2,%3}, {%4,%5,%6,%7}, {%8,%9}, {%0,%1,%2,%3};"
        : "+f"(c[0]), "+f"(c[1]), "+f"(c[2]), "+f"(c[3])
        : "r"(a[0]), "r"(a[1]), "r"(a[2]), "r"(a[3]), "r"(b0), "r"(b1));
}

// ---------------- convert kernels ----------------
__global__ __launch_bounds__(256)
void conv_x_kernel(const float* __restrict__ src) {
    size_t i8 = ((size_t)blockIdx.x * 256 + threadIdx.x) * 8;
    const float4* s = (const float4*)(src + i8);
    float f[8];
    *(float4*)(f + 0) = s[0];
    *(float4*)(f + 4) = s[1];
    __half h[8];
#pragma unroll
    for (int i = 0; i < 8; i++) h[i] = __float2half(f[i]);
    *(uint4*)(g_x + i8) = *(const uint4*)h;
}

__global__ __launch_bounds__(256)
void conv_w_kernel(const float* __restrict__ wf, const float* __restrict__ wg,
                   const float* __restrict__ wh) {
    size_t i8 = ((size_t)blockIdx.x * 256 + threadIdx.x) * 8;
    int gate = (int)(i8 / WSZ);
    size_t off = i8 - (size_t)gate * WSZ;
    const float* src = (gate == 0) ? wf : (gate == 1) ? wg : wh;
    const float4* s = (const float4*)(src + off);
    float f[8];
    *(float4*)(f + 0) = s[0];
    *(float4*)(f + 4) = s[1];
    __half h[8];
#pragma unroll
    for (int i = 0; i < 8; i++) h[i] = __float2half(f[i]);
    *(uint4*)(g_w + i8) = *(const uint4*)h;
}

// ---------------- step kernel ----------------
extern __shared__ char s_raw[];

__global__ __launch_bounds__(THREADS, 1)
void lnn_step(const float* __restrict__ bf, const float* __restrict__ bg,
              const float* __restrict__ bh, int t, int dst, int nchunks)
{
    const int tid  = threadIdx.x;
    const int wid  = tid >> 5;
    const int lane = tid & 31;
    const int wm   = wid & 3;      // 0..3  (M)
    const int wn   = wid >> 2;     // 0..1  (N)
    const int m0   = blockIdx.x * BM;
    const int n0   = blockIdx.y * BN;

    const __half* hin = g_h[dst ^ 1];

    float* sb = (float*)s_raw;                      // sb[3][64]
    if (tid < 192) {
        int g = tid >> 6, j = tid & 63;
        const float* b = (g == 0) ? bf : (g == 1) ? bg : bh;
        sb[tid] = b[n0 + j];
    }

    const uint32_t tiles = smem_u32(s_raw) + TILES_OFF;

    // ---- stage fill (cp.async), BK=64: 16B chunks, 8 per row ----
    auto fill = [&](int buf, int k0) {
        const uint32_t stg = tiles + buf * STAGE;
        const bool inx = (k0 < DIN);
#pragma unroll
        for (int it = 0; it < 4; it++) {            // A: 1024 x 16B
            int i = tid + it * THREADS;
            int r = i >> 3, c = i & 7;
            uint32_t d = stg + OFF_A + r * PITCH + c * 16;
            const __half* s;
            if (inx)
                s = g_x + (size_t)(m0 + r) * (SEQ * DIN) + (size_t)t * DIN + k0 + c * 8;
            else
                s = hin + (size_t)(m0 + r) * HID + (k0 - DIN) + c * 8;
            cp16(d, s);
        }
#pragma unroll
        for (int it = 0; it < 6; it++) {            // B: 1536 x 16B (3 gates)
            int i = tid + it * THREADS;
            int g = i >> 9, r = (i >> 3) & 63, c = i & 7;
            uint32_t d = stg + OFF_B + g * B_TILE + r * PITCH + c * 16;
            const __half* s = g_w + (size_t)g * WSZ + (size_t)(n0 + r) * CIN + k0 + c * 8;
            cp16(d, s);
        }
        cp_commit();
    };

    float acc[3][2][4][4];
#pragma unroll
    for (int g = 0; g < 3; g++)
#pragma unroll
        for (int mt = 0; mt < 2; mt++)
#pragma unroll
            for (int nt = 0; nt < 4; nt++)
#pragma unroll
                for (int r = 0; r < 4; r++) acc[g][mt][nt][r] = 0.f;

    // per-thread ldmatrix base offsets
    const uint32_t aoff = (uint32_t)((wm * 32 + (lane & 15)) * PITCH + (lane >> 4) * 16);
    const uint32_t boff = (uint32_t)((wn * 32 + (lane & 7) + ((lane >> 4) << 3)) * PITCH
                                     + ((lane >> 3) & 1) * 16);

    // fragment buffers: A and gate-0 B double-buffered across k16; B1/B2 single
    uint32_t afr[2][2][4];                  // [buf][mt][4]
    uint32_t b0[2][2][4];                   // [buf][nt2][4]
    uint32_t b1[2][4], b2[2][4];

    // 8 MMAs: one pass over the full warp tile for gate g
    auto prodA = [&](int g, uint32_t a[2][4], uint32_t b[2][4]) {
#pragma unroll
        for (int mt = 0; mt < 2; mt++)
#pragma unroll
            for (int nt = 0; nt < 4; nt++) {
                const int n2 = nt >> 1, br = (nt & 1) * 2;
                mma16816(acc[g][mt][nt], a[mt], b[n2][br], b[n2][br + 1]);
            }
    };

    fill(0, 0);
    for (int ch = 0; ch < nchunks; ch++) {
        cp_wait<0>();
        __syncthreads();                 // single barrier per chunk
        if (ch + 1 < nchunks) fill((ch + 1) & 1, (ch + 1) * BK);

        const uint32_t stg = tiles + (ch & 1) * STAGE;

        // prologue for k16 = 0
#pragma unroll
        for (int mt = 0; mt < 2; mt++)
            ldmx4(afr[0][mt], stg + OFF_A + mt * (16 * PITCH) + aoff);
        {
            uint32_t bb = stg + OFF_B + boff;
            ldmx4(b0[0][0], bb);
            ldmx4(b0[0][1], bb + 16 * PITCH);
        }

#pragma unroll
        for (int k16 = 0; k16 < 4; k16++) {
            const int cur = k16 & 1, nxt = cur ^ 1;
            const uint32_t kb  = k16 * 32;
            const uint32_t kbn = kb + 32;

            // gate 0 (B0 from regs), interleave B1 loads
            prodA(0, afr[cur], b0[cur]);
            {
                uint32_t bb = stg + OFF_B + 1 * B_TILE + kb + boff;
                ldmx4(b1[0], bb);
                ldmx4(b1[1], bb + 16 * PITCH);
            }

            // gate 1, interleave B2 + next-A loads
            prodA(1, afr[cur], b1);
            {
                uint32_t bb = stg + OFF_B + 2 * B_TILE + kb + boff;
                ldmx4(b2[0], bb);
                ldmx4(b2[1], bb + 16 * PITCH);
            }
            if (k16 < 3) {
#pragma unroll
                for (int mt = 0; mt < 2; mt++)
                    ldmx4(afr[nxt][mt], stg + OFF_A + mt * (16 * PITCH) + kbn + aoff);
            }

            // gate 2, interleave next-B0 loads
            prodA(2, afr[cur], b2);
            if (k16 < 3) {
                uint32_t bb = stg + OFF_B + kbn + boff;
                ldmx4(b0[nxt][0], bb);
                ldmx4(b0[nxt][1], bb + 16 * PITCH);
            }
        }
    }

    // ---- epilogue: bias + sigmoid gate, write h (single fp16) ----
    __half* hout = g_h[dst];
#pragma unroll
    for (int mt = 0; mt < 2; mt++)
#pragma unroll
        for (int nt = 0; nt < 4; nt++)
#pragma unroll
            for (int rh = 0; rh < 2; rh++) {
                const int row  = m0 + wm * 32 + mt * 16 + (lane >> 2) + rh * 8;
                const int colb = wn * 32 + nt * 8 + (lane & 3) * 2;   // block-local
                __half v[2];
#pragma unroll
                for (int q = 0; q < 2; q++) {
                    const float fo = acc[0][mt][nt][2 * rh + q] + sb[colb + q];
                    const float go = acc[1][mt][nt][2 * rh + q] + sb[64 + colb + q];
                    const float ho = acc[2][mt][nt][2 * rh + q] + sb[128 + colb + q];
                    const float gate = 1.0f / (1.0f + __expf(fo));    // sigmoid(-f)
                    v[q] = __float2half(gate * go + (1.0f - gate) * ho);
                }
                *(uint32_t*)(hout + (size_t)row * HID + n0 + colb) = *(const uint32_t*)v;
            }
}

// ---------------- FC head ----------------
__global__ __launch_bounds__(256)
void lnn_fc(const float* __restrict__ Wfc, const float* __restrict__ bfc,
            float* __restrict__ out, int src)
{
    const int b = blockIdx.x * blockDim.x + threadIdx.x;
    if (b >= BATCH) return;
    const __half* h = g_h[src] + (size_t)b * HID;
    const float* w0 = Wfc;
    const float* w1 = Wfc + HID;
    float s0 = 0.f, s1 = 0.f;
#pragma unroll 8
    for (int i = 0; i < HID; i++) {
        float hv = __half2float(h[i]);
        s0 += hv * w0[i];
        s1 += hv * w1[i];
    }
    out[b * 2 + 0] = s0 + bfc[0];
    out[b * 2 + 1] = s1 + bfc[1];
}

// ---------------- launch ----------------
extern "C" void kernel_launch(void* const* d_in, const int* in_sizes, int n_in,
                              void* d_out, int out_size)
{
    const float* x   = (const float*)d_in[0];
    const float* Wf  = (const float*)d_in[1];
    const float* bf  = (const float*)d_in[2];
    const float* Wg  = (const float*)d_in[3];
    const float* bg  = (const float*)d_in[4];
    const float* Wh  = (const float*)d_in[5];
    const float* bh  = (const float*)d_in[6];
    const float* Wfc = (const float*)d_in[7];
    const float* bfc = (const float*)d_in[8];
    float* out = (float*)d_out;

    cudaFuncSetAttribute(lnn_step, cudaFuncAttributeMaxDynamicSharedMemorySize, SMEM_DYN);

    conv_x_kernel<<<(BATCH * SEQ * DIN) / 2048, 256>>>(x);
    conv_w_kernel<<<(3 * WSZ) / 2048, 256>>>(Wf, Wg, Wh);

    dim3 grid(BATCH / BM, HID / BN);   // 16 x 16 = 256 CTAs
    for (int t = 0; t < SEQ; t++) {
        lnn_step<<<grid, THREADS, SMEM_DYN>>>(bf, bg, bh, t, t & 1,
                                              (t == 0) ? (DIN / BK) : (CIN / BK));
    }
    lnn_fc<<<BATCH / 256, 256>>>(Wfc, bfc, out, 1);
}